// round 1
// baseline (speedup 1.0000x reference)
#include <cuda_runtime.h>

// Conv2D 7x7 VALID on 4096x4096 fp32 -> 4090x4090, plus scalar bias.
// Strategy: y-register-blocked direct conv.
//   - Block = 128 threads, each thread computes one output column x 16 rows.
//   - Input tile (134 x 22 words) staged in shared memory, pitch 136.
//   - Per kx (7 passes): load a 22-tall register column, then 7x16 FMAs.
//     -> smem read traffic = 7*22/16 ~= 9.6 words/output (vs 49 naive).
//   - All 49 weights live in registers; stores lane-consecutive (coalesced).

#define KH 7
#define KW 7
#define H_IN 4096
#define W_IN 4096
#define H_OUT 4090
#define W_OUT 4090

#define TILE_X 128
#define TILE_Y 16
#define IN_W (TILE_X + KW - 1)   // 134
#define IN_H (TILE_Y + KH - 1)   // 22
#define PITCH 136                // 134 rounded up to multiple of 8 (16B align)

__global__ __launch_bounds__(TILE_X, 4)
void conv7x7_kernel(const float* __restrict__ X,
                    const float* __restrict__ Wt,
                    const float* __restrict__ bias,
                    float* __restrict__ out) {
    __shared__ float tile[IN_H * PITCH];

    const int tid = threadIdx.x;
    const int x0 = blockIdx.x * TILE_X;
    const int y0 = blockIdx.y * TILE_Y;

    // ---- weights + bias into registers (uniform-address broadcast loads) ----
    float w[KH * KW];
#pragma unroll
    for (int i = 0; i < KH * KW; i++) w[i] = __ldg(&Wt[i]);
    const float b = __ldg(&bias[0]);

    // ---- stage input tile: IN_H rows x 136 cols, float4 vectorized ----
    // x0 is a multiple of 128 and W_IN % 4 == 0, so a float4 at gx (mult of 4)
    // never straddles the row end: in-bounds iff gx < W_IN.
#pragma unroll 2
    for (int i = tid; i < IN_H * (PITCH / 4); i += TILE_X) {
        const int r  = i / (PITCH / 4);
        const int c4 = i % (PITCH / 4);
        const int gy = y0 + r;
        const int gx = x0 + c4 * 4;
        float4 val = make_float4(0.f, 0.f, 0.f, 0.f);
        if (gy < H_IN && gx < W_IN) {
            val = *reinterpret_cast<const float4*>(X + (size_t)gy * W_IN + gx);
        }
        *reinterpret_cast<float4*>(&tile[r * PITCH + c4 * 4]) = val;
    }
    __syncthreads();

    // ---- compute: one column per thread, 16 output rows in registers ----
    float acc[TILE_Y];
#pragma unroll
    for (int o = 0; o < TILE_Y; o++) acc[o] = 0.f;

#pragma unroll
    for (int kx = 0; kx < KW; kx++) {
        // Register column for input column (tid + kx): 22 values.
        // Lane-consecutive addresses -> conflict-free LDS.
        float v[IN_H];
#pragma unroll
        for (int j = 0; j < IN_H; j++) {
            v[j] = tile[j * PITCH + tid + kx];
        }
#pragma unroll
        for (int ky = 0; ky < KH; ky++) {
            const float wv = w[ky * KW + kx];
#pragma unroll
            for (int o = 0; o < TILE_Y; o++) {
                acc[o] = fmaf(v[o + ky], wv, acc[o]);
            }
        }
    }

    // ---- store: lanes write consecutive columns -> fully coalesced ----
    const int xo = x0 + tid;
    if (xo < W_OUT) {
#pragma unroll
        for (int o = 0; o < TILE_Y; o++) {
            const int yo = y0 + o;
            if (yo < H_OUT) {
                out[(size_t)yo * W_OUT + xo] = acc[o] + b;
            }
        }
    }
}

extern "C" void kernel_launch(void* const* d_in, const int* in_sizes, int n_in,
                              void* d_out, int out_size) {
    const float* X    = (const float*)d_in[0];
    const float* Wt   = (const float*)d_in[1];
    const float* bias = (const float*)d_in[2];
    float* out = (float*)d_out;

    dim3 grid((W_OUT + TILE_X - 1) / TILE_X,   // 32
              (H_OUT + TILE_Y - 1) / TILE_Y);  // 256
    dim3 block(TILE_X);
    conv7x7_kernel<<<grid, block>>>(X, Wt, bias, out);
}

// round 2
// speedup vs baseline: 1.2955x; 1.2955x over previous
#include <cuda_runtime.h>

// Conv2D 7x7 VALID, 4096x4096 fp32 -> 4090x4090, + scalar bias.
// v2: 4x8 register-blocked outputs per thread, vectorized LDS.128 with
// sliding-window register reuse (kx shifts are free register addressing).
//   - Block 128 threads = 32 (x) x 4 (y); block tile 128x32 outputs.
//   - Input tile 38 x 136 fp32 in smem (float4 staged, conflict-free).
//   - Per input row: 3 x ld.shared.v4 -> v[12]; 7x7x4 FFMA reuse.
//   - 42 LDS.128 + 1568 FFMA per thread (1.31 LDS-instr / output).

#define KH 7
#define KW 7
#define H_IN 4096
#define W_IN 4096
#define H_OUT 4090
#define W_OUT 4090

#define TILE_W 128          // block output tile width
#define TILE_H 32           // block output tile height
#define OX 4                // outputs per thread, x
#define OY 8                // outputs per thread, y
#define IN_H (TILE_H + KH - 1)   // 38
#define PITCH 136                // >= TILE_W + 6, multiple of 4 (16B align)

__global__ __launch_bounds__(128, 4)
void conv7x7_v2(const float* __restrict__ X,
                const float* __restrict__ Wt,
                const float* __restrict__ bias,
                float* __restrict__ out) {
    __shared__ float tile[IN_H * PITCH];

    const int tid = threadIdx.x;
    const int tx  = tid & 31;          // 0..31  (x within block)
    const int ty  = tid >> 5;          // 0..3   (y within block)
    const int x0  = blockIdx.x * TILE_W;
    const int y0  = blockIdx.y * TILE_H;

    // ---- weights + bias in registers ----
    float w[KH * KW];
#pragma unroll
    for (int i = 0; i < KH * KW; i++) w[i] = __ldg(&Wt[i]);
    const float b = __ldg(&bias[0]);

    // ---- stage input tile (38 x 136), float4 coalesced ----
    const bool interior_in = (x0 + PITCH <= W_IN) && (y0 + IN_H <= H_IN);
    if (interior_in) {
#pragma unroll
        for (int i = tid; i < IN_H * (PITCH / 4); i += 128) {
            const int r  = i / (PITCH / 4);
            const int c4 = i % (PITCH / 4);
            *reinterpret_cast<float4*>(&tile[r * PITCH + c4 * 4]) =
                *reinterpret_cast<const float4*>(
                    X + (size_t)(y0 + r) * W_IN + x0 + c4 * 4);
        }
    } else {
        for (int i = tid; i < IN_H * (PITCH / 4); i += 128) {
            const int r  = i / (PITCH / 4);
            const int c4 = i % (PITCH / 4);
            const int gy = y0 + r;
            const int gx = x0 + c4 * 4;
            float4 val = make_float4(0.f, 0.f, 0.f, 0.f);
            // gx is a multiple of 4 and W_IN % 4 == 0, so a float4 never
            // straddles the row end: in-bounds iff gx < W_IN.
            if (gy < H_IN && gx < W_IN) {
                val = *reinterpret_cast<const float4*>(
                    X + (size_t)gy * W_IN + gx);
            }
            *reinterpret_cast<float4*>(&tile[r * PITCH + c4 * 4]) = val;
        }
    }
    __syncthreads();

    // ---- compute: 4x8 outputs per thread ----
    float acc[OY][OX];
#pragma unroll
    for (int oy = 0; oy < OY; oy++)
#pragma unroll
        for (int ox = 0; ox < OX; ox++) acc[oy][ox] = 0.f;

    const int cbase = tx * OX;         // thread's first output column in tile
    const int rbase = ty * OY;         // thread's first output row in tile

#pragma unroll
    for (int j = 0; j < OY + KH - 1; j++) {      // 14 input rows
        // 12-word sliding window: columns cbase .. cbase+11 (need up to +9)
        float v[12];
        const float* rowp = &tile[(rbase + j) * PITCH + cbase];
        float4 a0 = *reinterpret_cast<const float4*>(rowp + 0);
        float4 a1 = *reinterpret_cast<const float4*>(rowp + 4);
        float4 a2 = *reinterpret_cast<const float4*>(rowp + 8);
        v[0]=a0.x; v[1]=a0.y; v[2]=a0.z;  v[3]=a0.w;
        v[4]=a1.x; v[5]=a1.y; v[6]=a1.z;  v[7]=a1.w;
        v[8]=a2.x; v[9]=a2.y; v[10]=a2.z; v[11]=a2.w;

#pragma unroll
        for (int ky = 0; ky < KH; ky++) {
            const int oy = j - ky;
            if (oy >= 0 && oy < OY) {
#pragma unroll
                for (int kx = 0; kx < KW; kx++) {
                    const float wv = w[ky * KW + kx];
                    acc[oy][0] = fmaf(v[kx + 0], wv, acc[oy][0]);
                    acc[oy][1] = fmaf(v[kx + 1], wv, acc[oy][1]);
                    acc[oy][2] = fmaf(v[kx + 2], wv, acc[oy][2]);
                    acc[oy][3] = fmaf(v[kx + 3], wv, acc[oy][3]);
                }
            }
        }
    }

    // ---- store ----
    const int xo = x0 + cbase;
    const int yo0 = y0 + rbase;
    const bool interior_out = (x0 + TILE_W <= W_OUT) && (y0 + TILE_H <= H_OUT);
    if (interior_out) {
        // xo even, W_OUT even -> 8B-aligned: use float2 pairs
#pragma unroll
        for (int oy = 0; oy < OY; oy++) {
            float* op = out + (size_t)(yo0 + oy) * W_OUT + xo;
            float2 p0 = make_float2(acc[oy][0] + b, acc[oy][1] + b);
            float2 p1 = make_float2(acc[oy][2] + b, acc[oy][3] + b);
            *reinterpret_cast<float2*>(op + 0) = p0;
            *reinterpret_cast<float2*>(op + 2) = p1;
        }
    } else {
#pragma unroll
        for (int oy = 0; oy < OY; oy++) {
            const int yo = yo0 + oy;
            if (yo < H_OUT) {
#pragma unroll
                for (int ox = 0; ox < OX; ox++) {
                    const int xc = xo + ox;
                    if (xc < W_OUT) {
                        out[(size_t)yo * W_OUT + xc] = acc[oy][ox] + b;
                    }
                }
            }
        }
    }
}

extern "C" void kernel_launch(void* const* d_in, const int* in_sizes, int n_in,
                              void* d_out, int out_size) {
    const float* X    = (const float*)d_in[0];
    const float* Wt   = (const float*)d_in[1];
    const float* bias = (const float*)d_in[2];
    float* out = (float*)d_out;

    dim3 grid((W_OUT + TILE_W - 1) / TILE_W,   // 32
              (H_OUT + TILE_H - 1) / TILE_H);  // 128
    dim3 block(128);
    conv7x7_v2<<<grid, block>>>(X, Wt, bias, out);
}

// round 4
// speedup vs baseline: 1.3184x; 1.0177x over previous
#include <cuda_runtime.h>

// Conv2D 7x7 VALID, 4096x4096 fp32 -> 4090x4090, + scalar bias.
// v3b: packed f32x2 FMA (Blackwell FFMA2). Each thread computes 4x8 outputs
// as 2 f32x2 column-pairs x 8 rows. Per input row: 3 LDS.128 -> 12-word
// window, 9 mov.b64 packs -> overlapping pairs; FFMA2 count = 784 (half of
// v2's 1568 FFMA). Weights stay scalar; (w,w) pair formed by single-reg
// replication at use (saves ~49 regs vs pre-packed pairs).
// Bitwise-identical numerics (fma.rn per lane).

#define KH 7
#define KW 7
#define H_IN 4096
#define W_IN 4096
#define H_OUT 4090
#define W_OUT 4090

#define TILE_W 128
#define TILE_H 32
#define OX 4                     // outputs per thread, x (= 2 f32x2 pairs)
#define OY 8                     // outputs per thread, y
#define IN_H (TILE_H + KH - 1)   // 38
#define PITCH 136

typedef unsigned long long u64;

__device__ __forceinline__ u64 pack2(float lo, float hi) {
    u64 r;
    asm("mov.b64 %0, {%1, %2};" : "=l"(r) : "f"(lo), "f"(hi));
    return r;
}
__device__ __forceinline__ u64 rep2(float v) {
    // (v, v) from one 32-bit register
    u64 r;
    asm("mov.b64 %0, {%1, %1};" : "=l"(r) : "f"(v));
    return r;
}
__device__ __forceinline__ void unpack2(u64 p, float& lo, float& hi) {
    asm("mov.b64 {%0, %1}, %2;" : "=f"(lo), "=f"(hi) : "l"(p));
}
__device__ __forceinline__ void fma2(u64& d, u64 a, u64 b) {
    asm("fma.rn.f32x2 %0, %1, %2, %0;" : "+l"(d) : "l"(a), "l"(b));
}
__device__ __forceinline__ u64 add2(u64 a, u64 b) {
    u64 r;
    asm("add.rn.f32x2 %0, %1, %2;" : "=l"(r) : "l"(a), "l"(b));
    return r;
}

__global__ __launch_bounds__(128, 4)
void conv7x7_v3(const float* __restrict__ X,
                const float* __restrict__ Wt,
                const float* __restrict__ bias,
                float* __restrict__ out) {
    __shared__ float tile[IN_H * PITCH];

    const int tid = threadIdx.x;
    const int tx  = tid & 31;
    const int ty  = tid >> 5;
    const int x0  = blockIdx.x * TILE_W;
    const int y0  = blockIdx.y * TILE_H;

    // ---- weights (scalar) + bias in registers ----
    float w[KH * KW];
#pragma unroll
    for (int i = 0; i < KH * KW; i++) w[i] = __ldg(&Wt[i]);
    const float b = __ldg(&bias[0]);

    // ---- stage input tile (38 x 136), float4 coalesced ----
    const bool interior_in = (x0 + PITCH <= W_IN) && (y0 + IN_H <= H_IN);
    if (interior_in) {
#pragma unroll
        for (int i = tid; i < IN_H * (PITCH / 4); i += 128) {
            const int r  = i / (PITCH / 4);
            const int c4 = i % (PITCH / 4);
            *reinterpret_cast<float4*>(&tile[r * PITCH + c4 * 4]) =
                *reinterpret_cast<const float4*>(
                    X + (size_t)(y0 + r) * W_IN + x0 + c4 * 4);
        }
    } else {
        for (int i = tid; i < IN_H * (PITCH / 4); i += 128) {
            const int r  = i / (PITCH / 4);
            const int c4 = i % (PITCH / 4);
            const int gy = y0 + r;
            const int gx = x0 + c4 * 4;
            float4 val = make_float4(0.f, 0.f, 0.f, 0.f);
            // gx multiple of 4, W_IN % 4 == 0 -> float4 never straddles row end
            if (gy < H_IN && gx < W_IN) {
                val = *reinterpret_cast<const float4*>(
                    X + (size_t)gy * W_IN + gx);
            }
            *reinterpret_cast<float4*>(&tile[r * PITCH + c4 * 4]) = val;
        }
    }
    __syncthreads();

    // ---- compute: 2 f32x2 pairs x 8 rows per thread ----
    u64 acc2[OY][2];
#pragma unroll
    for (int oy = 0; oy < OY; oy++) {
        acc2[oy][0] = 0ull;
        acc2[oy][1] = 0ull;
    }

    const int cbase = tx * OX;
    const int rbase = ty * OY;

#pragma unroll
    for (int j = 0; j < OY + KH - 1; j++) {        // 14 input rows
        float v[12];
        const float* rowp = &tile[(rbase + j) * PITCH + cbase];
        float4 a0 = *reinterpret_cast<const float4*>(rowp + 0);
        float4 a1 = *reinterpret_cast<const float4*>(rowp + 4);
        float4 a2 = *reinterpret_cast<const float4*>(rowp + 8);
        v[0]=a0.x; v[1]=a0.y; v[2]=a0.z;  v[3]=a0.w;
        v[4]=a1.x; v[5]=a1.y; v[6]=a1.z;  v[7]=a1.w;
        v[8]=a2.x; v[9]=a2.y; v[10]=a2.z; v[11]=a2.w;

        // overlapping pairs (v[s], v[s+1]) for s = 0..8
        u64 p[9];
#pragma unroll
        for (int s = 0; s < 9; s++) p[s] = pack2(v[s], v[s + 1]);

#pragma unroll
        for (int ky = 0; ky < KH; ky++) {
            const int oy = j - ky;
            if (oy >= 0 && oy < OY) {
#pragma unroll
                for (int kx = 0; kx < KW; kx++) {
                    const u64 wp = rep2(w[ky * KW + kx]);
                    fma2(acc2[oy][0], p[kx],     wp);
                    fma2(acc2[oy][1], p[kx + 2], wp);
                }
            }
        }
    }

    // ---- store (packed bias add, 8-byte stores on interior) ----
    const int xo  = x0 + cbase;
    const int yo0 = y0 + rbase;
    const u64 b2  = rep2(b);
    const bool interior_out = (x0 + TILE_W <= W_OUT) && (y0 + TILE_H <= H_OUT);
    if (interior_out) {
#pragma unroll
        for (int oy = 0; oy < OY; oy++) {
            float* op = out + (size_t)(yo0 + oy) * W_OUT + xo;
            u64 r0 = add2(acc2[oy][0], b2);
            u64 r1 = add2(acc2[oy][1], b2);
            *reinterpret_cast<u64*>(op + 0) = r0;   // xo even, 8B aligned
            *reinterpret_cast<u64*>(op + 2) = r1;
        }
    } else {
#pragma unroll
        for (int oy = 0; oy < OY; oy++) {
            const int yo = yo0 + oy;
            if (yo < H_OUT) {
                float r[OX];
                unpack2(acc2[oy][0], r[0], r[1]);
                unpack2(acc2[oy][1], r[2], r[3]);
#pragma unroll
                for (int ox = 0; ox < OX; ox++) {
                    const int xc = xo + ox;
                    if (xc < W_OUT) {
                        out[(size_t)yo * W_OUT + xc] = r[ox] + b;
                    }
                }
            }
        }
    }
}

extern "C" void kernel_launch(void* const* d_in, const int* in_sizes, int n_in,
                              void* d_out, int out_size) {
    const float* X    = (const float*)d_in[0];
    const float* Wt   = (const float*)d_in[1];
    const float* bias = (const float*)d_in[2];
    float* out = (float*)d_out;

    dim3 grid((W_OUT + TILE_W - 1) / TILE_W,   // 32
              (H_OUT + TILE_H - 1) / TILE_H);  // 128
    dim3 block(128);
    conv7x7_v3<<<grid, block>>>(X, Wt, bias, out);
}